// round 1
// baseline (speedup 1.0000x reference)
#include <cuda_runtime.h>

// Chamfer distance: array1, array2 are [B=4, N=4096, D=3] fp32.
// out = 100 * mean_b( 0.5 * (mean_m min_n d2 + mean_n min_m d2) )
//     = (100 / (2*B*N)) * sum over all 2*B*N per-point nearest-neighbor sq-dists.
//
// Strategy: d2 = |a|^2 + |b|^2 - 2 a.b.  Precompute hneg = -0.5*|b|^2 into a
// smem float4 alongside (bx,by,bz). Then per pair: t = fma(ax,bx, fma(ay,by,
// fma(az,bz, hneg))) and track vmax = max(t); min d2 = |a|^2 - 2*vmax.
// 3 FFMA + 1 FMNMX per pair, one LDS.128 broadcast amortized over 2 outer
// points per thread. Inner dim split in 2 across blocks; partial mins go to a
// __device__ scratch (deterministic, no atomics); kernel 2 combines + reduces.

#define BATCH 4
#define NPTS 4096
#define BLK 128
#define PT 2                              // outer points per thread
#define OUTER_PER_BLOCK (BLK * PT)        // 256
#define NCHUNK (NPTS / OUTER_PER_BLOCK)   // 16
#define ISPLIT 2
#define ICHUNK (NPTS / ISPLIT)            // 2048

// scratch: partial min-d2 per (split, direction*batch*point)
__device__ float g_partial[ISPLIT][2 * BATCH * NPTS];

__global__ __launch_bounds__(BLK) void chamfer_main(
    const float* __restrict__ a1, const float* __restrict__ a2)
{
    __shared__ float4 sy[ICHUNK];   // 2048 * 16B = 32 KB

    const int z   = blockIdx.z;     // 0..7 = b*2 + dir
    const int b   = z >> 1;
    const int dir = z & 1;

    const float* xb = (dir ? a2 : a1) + (size_t)b * NPTS * 3;
    const float* yb = (dir ? a1 : a2) + (size_t)b * NPTS * 3
                      + (size_t)blockIdx.y * ICHUNK * 3;

    // cooperative smem fill: (y, -0.5*|y|^2)
    for (int i = threadIdx.x; i < ICHUNK; i += BLK) {
        float yx = yb[i * 3 + 0];
        float yy = yb[i * 3 + 1];
        float yz = yb[i * 3 + 2];
        sy[i] = make_float4(yx, yy, yz,
                            -0.5f * (yx * yx + yy * yy + yz * yz));
    }
    __syncthreads();

    const int n0 = blockIdx.x * OUTER_PER_BLOCK + threadIdx.x;
    const int n1 = n0 + BLK;

    const float ax0 = xb[n0 * 3 + 0], ay0 = xb[n0 * 3 + 1], az0 = xb[n0 * 3 + 2];
    const float ax1 = xb[n1 * 3 + 0], ay1 = xb[n1 * 3 + 1], az1 = xb[n1 * 3 + 2];
    const float s0 = ax0 * ax0 + ay0 * ay0 + az0 * az0;
    const float s1 = ax1 * ax1 + ay1 * ay1 + az1 * az1;

    // two max-accumulators per point to break the FMNMX dependency chain
    float m0a = -1e30f, m0b = -1e30f;
    float m1a = -1e30f, m1b = -1e30f;

#pragma unroll 4
    for (int i = 0; i < ICHUNK; i += 2) {
        const float4 p = sy[i];
        const float4 q = sy[i + 1];

        float t0 = fmaf(ax0, p.x, fmaf(ay0, p.y, fmaf(az0, p.z, p.w)));
        float u0 = fmaf(ax0, q.x, fmaf(ay0, q.y, fmaf(az0, q.z, q.w)));
        float t1 = fmaf(ax1, p.x, fmaf(ay1, p.y, fmaf(az1, p.z, p.w)));
        float u1 = fmaf(ax1, q.x, fmaf(ay1, q.y, fmaf(az1, q.z, q.w)));

        m0a = fmaxf(m0a, t0);
        m0b = fmaxf(m0b, u0);
        m1a = fmaxf(m1a, t1);
        m1b = fmaxf(m1b, u1);
    }

    const float d0 = s0 - 2.0f * fmaxf(m0a, m0b);
    const float d1 = s1 - 2.0f * fmaxf(m1a, m1b);

    float* outp = g_partial[blockIdx.y];
    outp[z * NPTS + n0] = d0;
    outp[z * NPTS + n1] = d1;
}

__global__ __launch_bounds__(256) void chamfer_reduce(float* __restrict__ out)
{
    __shared__ float red[256];
    const int total = 2 * BATCH * NPTS;   // 32768

    float s = 0.0f;
    for (int i = threadIdx.x; i < total; i += 256) {
        s += fminf(g_partial[0][i], g_partial[1][i]);
    }
    red[threadIdx.x] = s;
    __syncthreads();

#pragma unroll
    for (int k = 128; k > 0; k >>= 1) {
        if (threadIdx.x < k) red[threadIdx.x] += red[threadIdx.x + k];
        __syncthreads();
    }

    if (threadIdx.x == 0) {
        out[0] = red[0] * (100.0f / (2.0f * BATCH * NPTS));
    }
}

extern "C" void kernel_launch(void* const* d_in, const int* in_sizes, int n_in,
                              void* d_out, int out_size)
{
    const float* a1 = (const float*)d_in[0];
    const float* a2 = (const float*)d_in[1];
    float* out = (float*)d_out;

    dim3 grid(NCHUNK, ISPLIT, 2 * BATCH);   // 16 x 2 x 8 = 256 blocks
    chamfer_main<<<grid, BLK>>>(a1, a2);
    chamfer_reduce<<<1, 256>>>(out);
}

// round 2
// speedup vs baseline: 1.4039x; 1.4039x over previous
#include <cuda_runtime.h>

// Chamfer distance: array1, array2 [B=4, N=4096, D=3] fp32.
// out = (100 / (2*B*N)) * sum over all 2*B*N per-point nearest-neighbor sq-dists.
//
// d2 = |a|^2 + |b|^2 - 2 a.b.  smem holds (y, -0.5*|y|^2) as float4; per pair:
// t = fma(ax,yx, fma(ay,yy, fma(az,yz, w))), track max t; min d2 = |a|^2 - 2 max t.
// 3 FFMA + 1 FMNMX per pair; 1 broadcast LDS.128 amortized over PT=4 outer pts.
//
// Block (256 thr, grid 16x8 = 128 blocks = 1 wave) covers 256 outer points and
// the FULL 4096 inner points: 4 groups of 64 threads each own an inner quarter;
// inner dim also double-buffered in 2 smem passes (32KB tile, stays static).
// Groups min-combine via smem, then the block sum-reduces -> 1 float/block.
// Final kernel sums 128 floats.

#define BLK 256
#define GROUPS 4
#define GSIZE 64
#define PT 4
#define OUTER_PER_BLOCK 256   // GSIZE * PT
#define NCHUNK 16             // 4096 / OUTER_PER_BLOCK
#define PASS_PTS 2048
#define GROUP_PTS 512         // PASS_PTS / GROUPS
#define NPTS 4096
#define NBLOCKS 128           // NCHUNK * 8

__device__ float g_partial[NBLOCKS];

__global__ __launch_bounds__(BLK) void chamfer_main(
    const float* __restrict__ a1, const float* __restrict__ a2)
{
    __shared__ float4 sy[PASS_PTS];                       // 32 KB
    __shared__ float  s_part[GROUPS][OUTER_PER_BLOCK];    // 4 KB
    __shared__ float  s_red[8];

    const int t   = threadIdx.x;
    const int z   = blockIdx.y;          // 0..7 = b*2 + dir
    const int b   = z >> 1;
    const int dir = z & 1;

    const float* xb = (dir ? a2 : a1) + (size_t)b * NPTS * 3;
    const float* yb = (dir ? a1 : a2) + (size_t)b * NPTS * 3;

    const int g = t >> 6;                // inner-quarter group 0..3
    const int l = t & 63;

    // each thread owns PT=4 outer points: n0, n0+64, n0+128, n0+192
    const int n0 = blockIdx.x * OUTER_PER_BLOCK + l;
    float ax[PT], ay[PT], az[PT], sq[PT], m[PT];
#pragma unroll
    for (int k = 0; k < PT; k++) {
        const int n = n0 + k * GSIZE;
        ax[k] = xb[n * 3 + 0];
        ay[k] = xb[n * 3 + 1];
        az[k] = xb[n * 3 + 2];
        sq[k] = ax[k] * ax[k] + ay[k] * ay[k] + az[k] * az[k];
        m[k]  = -3.0e38f;
    }

#pragma unroll 1
    for (int pass = 0; pass < 2; pass++) {
        // cooperative smem fill: 2048 points via float4 gmem loads
        const float4* ysrc = (const float4*)yb + (size_t)pass * (PASS_PTS * 3 / 4);
        __syncthreads();   // previous pass fully consumed
        for (int q = t; q < PASS_PTS / 4; q += BLK) {
            const float4 f0 = ysrc[q * 3 + 0];
            const float4 f1 = ysrc[q * 3 + 1];
            const float4 f2 = ysrc[q * 3 + 2];
            sy[q * 4 + 0] = make_float4(f0.x, f0.y, f0.z,
                -0.5f * (f0.x * f0.x + f0.y * f0.y + f0.z * f0.z));
            sy[q * 4 + 1] = make_float4(f0.w, f1.x, f1.y,
                -0.5f * (f0.w * f0.w + f1.x * f1.x + f1.y * f1.y));
            sy[q * 4 + 2] = make_float4(f1.z, f1.w, f2.x,
                -0.5f * (f1.z * f1.z + f1.w * f1.w + f2.x * f2.x));
            sy[q * 4 + 3] = make_float4(f2.y, f2.z, f2.w,
                -0.5f * (f2.y * f2.y + f2.z * f2.z + f2.w * f2.w));
        }
        __syncthreads();

        const float4* syg = sy + g * GROUP_PTS;
#pragma unroll 4
        for (int i = 0; i < GROUP_PTS; i++) {
            const float4 p = syg[i];
#pragma unroll
            for (int k = 0; k < PT; k++) {
                const float tt = fmaf(ax[k], p.x,
                                 fmaf(ay[k], p.y,
                                 fmaf(az[k], p.z, p.w)));
                m[k] = fmaxf(m[k], tt);
            }
        }
    }

    // per-group partial min-d2 for this thread's 4 outer slots
#pragma unroll
    for (int k = 0; k < PT; k++)
        s_part[g][l + k * GSIZE] = sq[k] - 2.0f * m[k];
    __syncthreads();

    // combine across groups (final min per outer point), then block-sum
    float v = fminf(fminf(s_part[0][t], s_part[1][t]),
                    fminf(s_part[2][t], s_part[3][t]));
#pragma unroll
    for (int o = 16; o; o >>= 1) v += __shfl_down_sync(0xffffffffu, v, o);
    if ((t & 31) == 0) s_red[t >> 5] = v;
    __syncthreads();
    if (t < 8) {
        float r = s_red[t];
#pragma unroll
        for (int o = 4; o; o >>= 1) r += __shfl_down_sync(0x000000ffu, r, o);
        if (t == 0) g_partial[blockIdx.y * NCHUNK + blockIdx.x] = r;
    }
}

__global__ __launch_bounds__(128) void chamfer_reduce(float* __restrict__ out)
{
    __shared__ float sr[4];
    const int t = threadIdx.x;          // 128 threads
    float v = g_partial[t];
#pragma unroll
    for (int o = 16; o; o >>= 1) v += __shfl_down_sync(0xffffffffu, v, o);
    if ((t & 31) == 0) sr[t >> 5] = v;
    __syncthreads();
    if (t == 0)
        out[0] = (sr[0] + sr[1] + sr[2] + sr[3]) * (100.0f / 32768.0f);
}

extern "C" void kernel_launch(void* const* d_in, const int* in_sizes, int n_in,
                              void* d_out, int out_size)
{
    const float* a1 = (const float*)d_in[0];
    const float* a2 = (const float*)d_in[1];
    float* out = (float*)d_out;

    dim3 grid(NCHUNK, 8);               // 16 x 8 = 128 blocks, one wave
    chamfer_main<<<grid, BLK>>>(a1, a2);
    chamfer_reduce<<<1, 128>>>(out);
}